// round 11
// baseline (speedup 1.0000x reference)
#include <cuda_runtime.h>
#include <math.h>

#define S 1024
#define H 768
#define NHEADS 16
#define KVH 8
#define D 64
#define HQ 1024
#define QKV_N 2048
#define NE 64
#define TOPK 8
#define FF 3072
#define CAP 256
#define RMS_EPS 1e-6f
#define F32_EPS 1.1920929e-07f

#ifdef __CUDA_ARCH_FEAT_SM103_ALL
#define HAS_TC 1
#else
#define HAS_TC 0
#endif

// ---------------- scratch ----------------
__device__ float g_x1[S*H];
__device__ float g_qkv[S*QKV_N];
__device__ float g_q[NHEADS*S*D];
__device__ float g_k[KVH*S*D];
__device__ float g_v[KVH*S*D];
__device__ float g_attn[S*HQ];
__device__ float g_hidden[S*H];
__device__ float g_x2[S*H];
__device__ float g_act[S*FF];
__device__ float g_shared[S*H];
__device__ int   g_topi[S*TOPK];
__device__ float g_topw[S*TOPK];
__device__ int   g_slot[S*TOPK];
__device__ int   g_cnt[NE];
__device__ int   g_tok[NE*CAP];
__device__ float g_xd[NE*CAP*H];
__device__ float g_eact[NE*CAP*FF];
__device__ float g_eout[NE*CAP*H];

// ---------------- helpers ----------------
__device__ __forceinline__ float to_tf32(float x) {
    unsigned u;
    asm("cvt.rna.tf32.f32 %0, %1;" : "=r"(u) : "f"(x));
    return __uint_as_float(u);
}
__device__ __forceinline__ float4 cvt4(float4 v) {
    return make_float4(to_tf32(v.x), to_tf32(v.y), to_tf32(v.z), to_tf32(v.w));
}
// pack 4 floats -> 4 bf16 (rn), element order preserved (low halves first)
__device__ __forceinline__ uint2 f4_to_bf4(float4 v) {
    unsigned lo, hi;
    asm("cvt.rn.bf16x2.f32 %0, %1, %2;" : "=r"(lo) : "f"(v.y), "f"(v.x));
    asm("cvt.rn.bf16x2.f32 %0, %1, %2;" : "=r"(hi) : "f"(v.w), "f"(v.z));
    return make_uint2(lo, hi);
}
__device__ __forceinline__ unsigned smem_to_u32(const void* p) {
    unsigned addr;
    asm("{ .reg .u64 t;\n\t"
        "cvta.to.shared.u64 t, %1;\n\t"
        "cvt.u32.u64 %0, t; }"
        : "=r"(addr) : "l"(p));
    return addr;
}
__device__ __forceinline__ void mma_tf32(float* d, const float* a, const float* b) {
    asm volatile(
        "mma.sync.aligned.m16n8k8.row.col.f32.tf32.tf32.f32\n\t"
        "{%0,%1,%2,%3},\n\t"
        "{%4,%5,%6,%7},\n\t"
        "{%8,%9},\n\t"
        "{%0,%1,%2,%3};"
        : "+f"(d[0]), "+f"(d[1]), "+f"(d[2]), "+f"(d[3])
        : "r"(__float_as_uint(a[0])), "r"(__float_as_uint(a[1])),
          "r"(__float_as_uint(a[2])), "r"(__float_as_uint(a[3])),
          "r"(__float_as_uint(b[0])), "r"(__float_as_uint(b[1])));
}
__device__ __forceinline__ float silu_mul(float g, float u) {
    return g * (u / (1.f + __expf(-u)));
}

#define SMEM_SWIZZLE_128B(o) ((o) ^ (((o) >> 3) & 0x70))

#if HAS_TC
__device__ __forceinline__ unsigned long long make_desc(unsigned addr) {
    unsigned long long d = 0;
    d |= (unsigned long long)(addr >> 4) & 0x3FFFull;
    d |= 1ull << 16;
    d |= 64ull << 32;
    d |= 1ull << 46;
    d |= 2ull << 61;
    return d;
}
__device__ __forceinline__ void mbar_init(unsigned mbar, unsigned cnt) {
    asm volatile("mbarrier.init.shared.b64 [%0], %1;" :: "r"(mbar), "r"(cnt) : "memory");
}
__device__ __forceinline__ void mbar_wait(unsigned mbar, unsigned parity) {
    unsigned done;
    asm volatile(
        "{ .reg .pred p;\n\t"
        "mbarrier.try_wait.parity.acquire.cta.shared::cta.b64 p, [%1], %2;\n\t"
        "selp.b32 %0, 1, 0, p; }"
        : "=r"(done) : "r"(mbar), "r"(parity) : "memory");
    if (!done) {
        asm volatile(
            "{ .reg .pred p;\n\t"
            "LW%=:\n\t"
            "mbarrier.try_wait.parity.acquire.cta.shared::cta.b64 p, [%0], %1, 0x989680;\n\t"
            "@p bra.uni LD%=;\n\t"
            "bra.uni LW%=;\n\t"
            "LD%=: }"
            :: "r"(mbar), "r"(parity) : "memory");
    }
}
__device__ __forceinline__ void tc_alloc(unsigned smem_dst, unsigned ncols) {
    asm volatile(
        "tcgen05.alloc.cta_group::1.sync.aligned.shared::cta.b32 [%0], %1;"
        :: "r"(smem_dst), "r"(ncols) : "memory");
}
__device__ __forceinline__ void tc_dealloc(unsigned taddr, unsigned ncols) {
    asm volatile(
        "tcgen05.dealloc.cta_group::1.sync.aligned.b32 %0, %1;"
        :: "r"(taddr), "r"(ncols));
}
__device__ __forceinline__ void tc_relinquish() {
    asm volatile("tcgen05.relinquish_alloc_permit.cta_group::1.sync.aligned;");
}
__device__ __forceinline__ void tc_commit(unsigned mbar) {
    asm volatile(
        "tcgen05.commit.cta_group::1.mbarrier::arrive::one.shared::cluster.b64 [%0];"
        :: "r"(mbar) : "memory");
}
__device__ __forceinline__ void tc_fence_after() {
    asm volatile("tcgen05.fence::after_thread_sync;" ::: "memory");
}
__device__ __forceinline__ void tc_wait_ld() {
    asm volatile("tcgen05.wait::ld.sync.aligned;" ::: "memory");
}
__device__ __forceinline__ void fence_async() {
    asm volatile("fence.proxy.async.shared::cta;" ::: "memory");
}
__device__ __forceinline__ void tc_ld_x8(unsigned* r, unsigned taddr) {
    asm volatile(
        "tcgen05.ld.sync.aligned.32x32b.x8.b32\n\t"
        "{%0, %1, %2, %3, %4, %5, %6, %7}, [%8];"
        : "=r"(r[0]), "=r"(r[1]), "=r"(r[2]), "=r"(r[3]),
          "=r"(r[4]), "=r"(r[5]), "=r"(r[6]), "=r"(r[7])
        : "r"(taddr));
}
__device__ __forceinline__ void tc_mma_bf16(
    unsigned dtm, unsigned long long ad, unsigned long long bd,
    unsigned idesc, unsigned en)
{
    asm volatile(
        "{ .reg .pred p;\n\t"
        "setp.ne.u32 p, %4, 0;\n\t"
        "tcgen05.mma.cta_group::1.kind::f16 [%0], %1, %2, %3, p; }"
        :: "r"(dtm), "l"(ad), "l"(bd), "r"(idesc), "r"(en)
        : "memory");
}
#endif  // HAS_TC

// ---------------- dual-path GEMM (bf16 tcgen05, 128-row tiles) ----------------
// MODE 0: C = A*B^T.  MODE 1: C = A*B^T + Res.
// MODE 2 (SwiGLU): B-tile = 128 gate rows ++ 128 up rows; C = gate*silu(up). (NT=256)
#define TC_SMEM_BYTES(NT) (1024 + 2*16384 + 2*(NT)*128)

template <int NT, int MODE>
__global__ void __launch_bounds__(256) tc_gemm(
    const float* __restrict__ A, const float* __restrict__ B,
    const float* __restrict__ Res, float* __restrict__ C,
    int M, int N, int K,
    long long sA, long long sB, long long sC, const int* __restrict__ rowcnt)
{
    int bz = blockIdx.z;
    int row0 = blockIdx.y * 128;
    int col0 = blockIdx.x * ((MODE == 2) ? NT/2 : NT);
    if (rowcnt && row0 >= rowcnt[bz]) return;
    const float* Ab = A + (long long)bz * sA;
    const float* Bb = B + (long long)bz * sB;
    float* Cb = C + (long long)bz * sC;
    extern __shared__ char smem[];
    int tid = threadIdx.x, wid = tid >> 5, lane = tid & 31;

#if HAS_TC
    unsigned smem_base = smem_to_u32(smem);
    // bf16 idesc: dtype=F32, atype=btype=BF16, N, M=128 (validated vs 0x8080490)
    const unsigned IDESC = (1u<<4) | (1u<<7) | (1u<<10)
                         | ((unsigned)(NT>>3)<<17) | (8u<<24);
    if (wid == 0) { tc_alloc(smem_base, NT); tc_relinquish(); }
    if (tid == 0) { mbar_init(smem_base + 16, 1); mbar_init(smem_base + 24, 1); }
    __syncthreads();
    unsigned tmem_base = *(volatile unsigned*)smem;

    const int ABUF = 1024;
    const int BBUF = 1024 + 32768;
    const int BSZ = NT * 128;          // NT rows x 128B (64 bf16 per row)

    // staged bf16 data: A 8x uint2, B NT/16 x uint2
    uint2 av[8], bv[NT/16];
    auto load_chunk = [&](int ci) {
        int k0 = ci << 6;              // 64 bf16 K-elements per chunk
#pragma unroll
        for (int it = 0; it < 8; it++) {
            int idx = it * 256 + tid, r = idx >> 4, c = (idx & 15) * 4;
            av[it] = f4_to_bf4(*(const float4*)&Ab[(long long)(row0 + r) * K + k0 + c]);
        }
#pragma unroll
        for (int it = 0; it < NT/16; it++) {
            int idx = it * 256 + tid, r = idx >> 4, c = (idx & 15) * 4;
            int brow = (MODE == 2) ? ((r < NT/2) ? (col0 + r) : (FF + col0 + r - NT/2))
                                   : (col0 + r);
            bv[it] = f4_to_bf4(*(const float4*)&Bb[(long long)brow * K + k0 + c]);
        }
    };

    int nc = K >> 6;
    load_chunk(0);
    for (int i = 0; i < nc; i++) {
        int buf = i & 1;
        if (i >= 2) mbar_wait(smem_base + 16 + 8*buf, ((i-2)>>1) & 1);
        char* As = smem + ABUF + buf * 16384;
        char* Bs = smem + BBUF + buf * BSZ;
#pragma unroll
        for (int it = 0; it < 8; it++) {
            int idx = it * 256 + tid, r = idx >> 4, c = (idx & 15) * 4;
            unsigned off = (unsigned)(r * 128 + c * 2);
            *(uint2*)(As + SMEM_SWIZZLE_128B(off)) = av[it];
        }
#pragma unroll
        for (int it = 0; it < NT/16; it++) {
            int idx = it * 256 + tid, r = idx >> 4, c = (idx & 15) * 4;
            unsigned off = (unsigned)(r * 128 + c * 2);
            *(uint2*)(Bs + SMEM_SWIZZLE_128B(off)) = bv[it];
        }
        if (i + 1 < nc) load_chunk(i + 1);
        fence_async();
        __syncthreads();
        if (tid == 0) {
            unsigned long long ad = make_desc(smem_base + ABUF + buf*16384);
            unsigned long long bd = make_desc(smem_base + BBUF + buf*BSZ);
#pragma unroll
            for (int sub = 0; sub < 4; sub++)   // 4 x K=16 per 64-K chunk
                tc_mma_bf16(tmem_base, ad + sub*2, bd + sub*2, IDESC,
                            (i > 0 || sub > 0) ? 1u : 0u);
            tc_commit(smem_base + 16 + 8*buf);
        }
    }
    mbar_wait(smem_base + 16 + 8*((nc-2)&1), ((nc-2)>>1) & 1);
    mbar_wait(smem_base + 16 + 8*((nc-1)&1), ((nc-1)>>1) & 1);
    tc_fence_after();

    long long r = row0 + (wid & 3) * 32 + lane;
    if (MODE == 2) {
#pragma unroll
        for (int cc = 0; cc < 2; cc++) {
            int gc = (wid >> 2) * 2 + cc;
            unsigned gr[32], ur[32];
#pragma unroll
            for (int q = 0; q < 4; q++)
                tc_ld_x8(gr + q*8, tmem_base + gc*32 + q*8);
#pragma unroll
            for (int q = 0; q < 4; q++)
                tc_ld_x8(ur + q*8, tmem_base + 128 + gc*32 + q*8);
            tc_wait_ld();
            long long cbase = col0 + gc * 32;
            float vals[32];
#pragma unroll
            for (int j = 0; j < 32; j++)
                vals[j] = silu_mul(__uint_as_float(gr[j]), __uint_as_float(ur[j]));
#pragma unroll
            for (int j = 0; j < 32; j += 4)
                *(float4*)&Cb[r * N + cbase + j] =
                    make_float4(vals[j], vals[j+1], vals[j+2], vals[j+3]);
        }
    } else {
        const int CPW = NT / 64;
#pragma unroll
        for (int cc = 0; cc < CPW; cc++) {
            int chunk = (wid >> 2) * CPW + cc;
            unsigned regs[32];
#pragma unroll
            for (int q = 0; q < 4; q++)
                tc_ld_x8(regs + q*8, tmem_base + chunk*32 + q*8);
            tc_wait_ld();
            long long cbase = col0 + chunk * 32;
            float vals[32];
#pragma unroll
            for (int j = 0; j < 32; j++) vals[j] = __uint_as_float(regs[j]);
            if (MODE == 1) {
#pragma unroll
                for (int j = 0; j < 32; j++) vals[j] += Res[r * N + cbase + j];
            }
#pragma unroll
            for (int j = 0; j < 32; j += 4)
                *(float4*)&Cb[r * N + cbase + j] =
                    make_float4(vals[j], vals[j+1], vals[j+2], vals[j+3]);
        }
    }
    __syncthreads();
    if (wid == 0) tc_dealloc(tmem_base, NT);
#else
    // -------- fallback: mma.sync TF32 path (128x128 subtiles) --------
    int warp_m = wid >> 2, warp_n = wid & 3;
    float (*As)[8][4][32]  = (float(*)[8][4][32])smem;
    float (*Bs)[16][2][32] = (float(*)[16][2][32])(smem + 16384);
    float gate_st[4][4][4];
#pragma unroll
    for (int cb = 0; cb < NT/128; cb++) {
        const float* Ar = Ab + (long long)row0 * K;
        long long brow0 = (MODE == 2) ? ((cb == 0) ? col0 : (FF + col0))
                                      : (col0 + cb*128);
        const float* Br = Bb + brow0 * K;
        float acc[4][4][4];
#pragma unroll
        for (int mi = 0; mi < 4; mi++)
#pragma unroll
            for (int ni = 0; ni < 4; ni++)
#pragma unroll
                for (int rr = 0; rr < 4; rr++) acc[mi][ni][rr] = 0.f;
        float4 areg[4], breg[4];
#pragma unroll
        for (int it = 0; it < 4; it++) {
            int idx = it * 256 + tid, r = idx >> 3, c4 = (idx & 7) * 4;
            areg[it] = *(const float4*)&Ar[(long long)r * K + c4];
            breg[it] = *(const float4*)&Br[(long long)r * K + c4];
        }
        for (int k0 = 0; k0 < K; k0 += 32) {
#pragma unroll
            for (int it = 0; it < 4; it++) {
                int idx = it * 256 + tid, r = idx >> 3, k4 = (idx & 7) * 4;
                int kstep = k4 >> 3, khi = (k4 & 7) >> 2;
                int mtile = r >> 4, rr2 = r & 15, gA = rr2 & 7, hi = rr2 >> 3;
                *(float4*)&As[kstep][mtile][hi + 2*khi][gA * 4] = cvt4(areg[it]);
                int ntile = r >> 3, gB = r & 7;
                *(float4*)&Bs[kstep][ntile][khi][gB * 4] = cvt4(breg[it]);
            }
            __syncthreads();
            if (k0 + 32 < K) {
#pragma unroll
                for (int it = 0; it < 4; it++) {
                    int idx = it * 256 + tid, r = idx >> 3, c4 = (idx & 7) * 4;
                    areg[it] = *(const float4*)&Ar[(long long)r * K + k0 + 32 + c4];
                    breg[it] = *(const float4*)&Br[(long long)r * K + k0 + 32 + c4];
                }
            }
#pragma unroll
            for (int kstep = 0; kstep < 4; kstep++) {
                float a[4][4], b[4][2];
#pragma unroll
                for (int mi = 0; mi < 4; mi++)
#pragma unroll
                    for (int rr = 0; rr < 4; rr++)
                        a[mi][rr] = As[kstep][warp_m * 4 + mi][rr][lane];
#pragma unroll
                for (int ni = 0; ni < 4; ni++)
#pragma unroll
                    for (int rr = 0; rr < 2; rr++)
                        b[ni][rr] = Bs[kstep][warp_n * 4 + ni][rr][lane];
#pragma unroll
                for (int mi = 0; mi < 4; mi++)
#pragma unroll
                    for (int ni = 0; ni < 4; ni++)
                        mma_tf32(acc[mi][ni], a[mi], b[ni]);
            }
            __syncthreads();
        }
        if (MODE == 2 && cb == 0) {
#pragma unroll
            for (int mi = 0; mi < 4; mi++)
#pragma unroll
                for (int ni = 0; ni < 4; ni++)
#pragma unroll
                    for (int rr = 0; rr < 4; rr++)
                        gate_st[mi][ni][rr] = acc[mi][ni][rr];
            continue;
        }
        int g = lane >> 2, c = lane & 3;
#pragma unroll
        for (int mi = 0; mi < 4; mi++) {
#pragma unroll
            for (int ni = 0; ni < 4; ni++) {
                long long row = row0 + warp_m * 64 + mi * 16 + g;
                long long col = col0 + ((MODE == 2) ? 0 : cb*128)
                              + warp_n * 32 + ni * 8 + c * 2;
                float v0, v1, v2, v3;
                if (MODE == 2) {
                    v0 = silu_mul(gate_st[mi][ni][0], acc[mi][ni][0]);
                    v1 = silu_mul(gate_st[mi][ni][1], acc[mi][ni][1]);
                    v2 = silu_mul(gate_st[mi][ni][2], acc[mi][ni][2]);
                    v3 = silu_mul(gate_st[mi][ni][3], acc[mi][ni][3]);
                } else {
                    v0 = acc[mi][ni][0]; v1 = acc[mi][ni][1];
                    v2 = acc[mi][ni][2]; v3 = acc[mi][ni][3];
                    if (MODE == 1) {
                        v0 += Res[row * N + col];       v1 += Res[row * N + col + 1];
                        v2 += Res[(row + 8) * N + col]; v3 += Res[(row + 8) * N + col + 1];
                    }
                }
                *(float2*)&Cb[row * N + col]       = make_float2(v0, v1);
                *(float2*)&Cb[(row + 8) * N + col] = make_float2(v2, v3);
            }
        }
    }
#endif
}

// ---------------- RMSNorm over H ----------------
__global__ void rmsnorm_kernel(const float* __restrict__ in, const float* __restrict__ w,
                               float* __restrict__ out) {
    int s = blockIdx.x;
    const float* row = in + (long long)s * H;
    __shared__ float red[8];
    float ss = 0.f;
    for (int i = threadIdx.x; i < H; i += blockDim.x) { float v = row[i]; ss += v * v; }
    for (int o = 16; o; o >>= 1) ss += __shfl_down_sync(0xffffffffu, ss, o);
    if ((threadIdx.x & 31) == 0) red[threadIdx.x >> 5] = ss;
    __syncthreads();
    if (threadIdx.x == 0) {
        float t = 0.f;
        for (int i = 0; i < (int)(blockDim.x >> 5); i++) t += red[i];
        red[0] = t;
    }
    __syncthreads();
    float inv = rsqrtf(red[0] / (float)H + RMS_EPS);
    for (int i = threadIdx.x; i < H; i += blockDim.x)
        out[(long long)s * H + i] = w[i] * (row[i] * inv);
}

// ---------------- RoPE + per-head RMSNorm, split qkv ----------------
__global__ void rope_norm_kernel(const float* __restrict__ cosb, const float* __restrict__ sinb,
                                 const float* __restrict__ qw, const float* __restrict__ kw) {
    int u = blockIdx.x, s = blockIdx.y, d = threadIdx.x;
    if (u >= 24) {
        int kvh = u - 24;
        g_v[((long long)kvh * S + s) * D + d] = g_qkv[(long long)s * QKV_N + (kvh * 4 + 3) * D + d];
        return;
    }
    int n; const float* w; float* dst;
    if (u < 16) {
        int kvh = u >> 1, j = u & 1;
        n = (kvh * 4 + j) * D + d; w = qw;
        dst = &g_q[((long long)u * S + s) * D + d];
    } else {
        int kvh = u - 16;
        n = (kvh * 4 + 2) * D + d; w = kw;
        dst = &g_k[((long long)kvh * S + s) * D + d];
    }
    float val = g_qkv[(long long)s * QKV_N + n];
    float other = (d < 32) ? -g_qkv[(long long)s * QKV_N + n + 32]
                           :  g_qkv[(long long)s * QKV_N + n - 32];
    float r = val * cosb[(long long)s * D + d] + other * sinb[(long long)s * D + d];
    float ss = r * r;
    for (int o = 16; o; o >>= 1) ss += __shfl_xor_sync(0xffffffffu, ss, o);
    __shared__ float sh[2];
    if ((d & 31) == 0) sh[d >> 5] = ss;
    __syncthreads();
    float inv = rsqrtf((sh[0] + sh[1]) / (float)D + RMS_EPS);
    *dst = w[d] * (r * inv);
}

// ---------------- tensor-core causal flash attention ----------------
__global__ void __launch_bounds__(128) attn_kernel() {
    int qb = gridDim.x - 1 - blockIdx.x;
    int h = blockIdx.y, kvh = h >> 1;
    int tid = threadIdx.x, wid = tid >> 5, lane = tid & 31;
    int g = lane >> 2, qt = lane & 3;

    __shared__ float Qs[64][64];
    __shared__ float Bqk[8][4][2][32];
    __shared__ float Bpv[4][8][2][32];

    const float* qbase = g_q + ((long long)h * S + qb * 64) * D;
    for (int i = tid; i < 64 * 64; i += 128)
        Qs[i >> 6][i & 63] = to_tf32(qbase[i] * 0.125f);
    __syncthreads();

    float a_q[8][4];
#pragma unroll
    for (int ks = 0; ks < 8; ks++) {
        a_q[ks][0] = Qs[wid*16 + g    ][ks*8 + qt];
        a_q[ks][1] = Qs[wid*16 + g + 8][ks*8 + qt];
        a_q[ks][2] = Qs[wid*16 + g    ][ks*8 + 4 + qt];
        a_q[ks][3] = Qs[wid*16 + g + 8][ks*8 + 4 + qt];
    }

    float acc_o[8][4];
#pragma unroll
    for (int d2 = 0; d2 < 8; d2++)
#pragma unroll
        for (int r = 0; r < 4; r++) acc_o[d2][r] = 0.f;

    float m0 = -1e30f, m1 = -1e30f, l0 = 0.f, l1 = 0.f;
    int gq0 = qb*64 + wid*16 + g;
    int gq1 = gq0 + 8;
    int nkt = 2*qb + 2;

    for (int kt = 0; kt < nkt; kt++) {
        int kbase = kt * 32;
        __syncthreads();
        const float* kptr = g_k + ((long long)kvh * S + kbase) * D;
        for (int i = tid; i < 512; i += 128) {
            int r = i >> 4, c4 = (i & 15) * 4;
            float4 v = cvt4(*(const float4*)&kptr[r*64 + c4]);
            *(float4*)&Bqk[c4 >> 3][r >> 3][(c4 >> 2) & 1][(r & 7) * 4] = v;
        }
        const float* vptr = g_v + ((long long)kvh * S + kbase) * D;
        for (int i = tid; i < 512; i += 128) {
            int r = i >> 4, c4 = (i & 15) * 4;
            float4 v = cvt4(*(const float4*)&vptr[r*64 + c4]);
            int ks = r >> 3, reg = (r >> 2) & 1;
            int nt = c4 >> 3, lb = (c4 & 7) * 4 + (r & 3);
            Bpv[ks][nt][reg][lb]      = v.x;
            Bpv[ks][nt][reg][lb + 4]  = v.y;
            Bpv[ks][nt][reg][lb + 8]  = v.z;
            Bpv[ks][nt][reg][lb + 12] = v.w;
        }
        __syncthreads();

        float sacc[4][4];
#pragma unroll
        for (int nt = 0; nt < 4; nt++)
#pragma unroll
            for (int r = 0; r < 4; r++) sacc[nt][r] = 0.f;
#pragma unroll
        for (int nt = 0; nt < 4; nt++)
#pragma unroll
            for (int ks = 0; ks < 8; ks++) {
                float b[2] = { Bqk[ks][nt][0][lane], Bqk[ks][nt][1][lane] };
                mma_tf32(sacc[nt], a_q[ks], b);
            }

        float mn0 = m0, mn1 = m1;
#pragma unroll
        for (int nt = 0; nt < 4; nt++) {
            int col = kbase + nt*8 + 2*qt;
            if (col     > gq0) sacc[nt][0] = -1e30f;
            if (col + 1 > gq0) sacc[nt][1] = -1e30f;
            if (col     > gq1) sacc[nt][2] = -1e30f;
            if (col + 1 > gq1) sacc[nt][3] = -1e30f;
            mn0 = fmaxf(mn0, fmaxf(sacc[nt][0], sacc[nt][1]));
            mn1 = fmaxf(mn1, fmaxf(sacc[nt][2], sacc[nt][3]));
        }
        mn0 = fmaxf(mn0, __shfl_xor_sync(0xffffffffu, mn0, 1));
        mn0 = fmaxf(mn0, __shfl_xor_sync(0xffffffffu, mn0, 2));
        mn1 = fmaxf(mn1, __shfl_xor_sync(0xffffffffu, mn1, 1));
        mn1 = fmaxf(mn1, __shfl_xor_sync(0xffffffffu, mn1, 2));

        float al0 = __expf(m0 - mn0), al1 = __expf(m1 - mn1);
        float rs0 = 0.f, rs1 = 0.f;
#pragma unroll
        for (int nt = 0; nt < 4; nt++) {
            sacc[nt][0] = __expf(sacc[nt][0] - mn0);
            sacc[nt][1] = __expf(sacc[nt][1] - mn0);
            sacc[nt][2] = __expf(sacc[nt][2] - mn1);
            sacc[nt][3] = __expf(sacc[nt][3] - mn1);
            rs0 += sacc[nt][0] + sacc[nt][1];
            rs1 += sacc[nt][2] + sacc[nt][3];
        }
        rs0 += __shfl_xor_sync(0xffffffffu, rs0, 1);
        rs0 += __shfl_xor_sync(0xffffffffu, rs0, 2);
        rs1 += __shfl_xor_sync(0xffffffffu, rs1, 1);
        rs1 += __shfl_xor_sync(0xffffffffu, rs1, 2);
        l0 = l0 * al0 + rs0;
        l1 = l1 * al1 + rs1;
        m0 = mn0; m1 = mn1;

#pragma unroll
        for (int d2 = 0; d2 < 8; d2++) {
            acc_o[d2][0] *= al0; acc_o[d2][1] *= al0;
            acc_o[d2][2] *= al1; acc_o[d2][3] *= al1;
        }

        float a_p[4][4];
        int base = lane & ~3;
        int s1 = base + (qt >> 1);
        int s2 = base + 2 + (qt >> 1);
        bool odd = (qt & 1) != 0;
#pragma unroll
        for (int ks = 0; ks < 4; ks++) {
            float u0 = __shfl_sync(0xffffffffu, sacc[ks][0], s1);
            float u1 = __shfl_sync(0xffffffffu, sacc[ks][1], s1);
            float u2 = __shfl_sync(0xffffffffu, sacc[ks][2], s1);
            float u3 = __shfl_sync(0xffffffffu, sacc[ks][3], s1);
            float w0 = __shfl_sync(0xffffffffu, sacc[ks][0], s2);
            float w1 = __shfl_sync(0xffffffffu, sacc[ks][1], s2);
            float w2 = __shfl_sync(0xffffffffu, sacc[ks][2], s2);
            float w3 = __shfl_sync(0xffffffffu, sacc[ks][3], s2);
            a_p[ks][0] = to_tf32(odd ? u1 : u0);
            a_p[ks][1] = to_tf32(odd ? u3 : u2);
            a_p[ks][2] = to_tf32(odd ? w1 : w0);
            a_p[ks][3] = to_tf32(odd ? w3 : w2);
        }

#pragma unroll
        for (int d2 = 0; d2 < 8; d2++)
#pragma unroll
            for (int ks = 0; ks < 4; ks++) {
                float b[2] = { Bpv[ks][d2][0][lane], Bpv[ks][d2][1][lane] };
                mma_tf32(acc_o[d2], a_p[ks], b);
            }
    }

    float inv0 = 1.f / l0, inv1 = 1.f / l1;
    float* o0 = g_attn + (long long)gq0 * HQ + h * D;
    float* o1 = g_attn + (long long)gq1 * HQ + h * D;
#pragma unroll
    for (int d2 = 0; d2 < 8; d2++) {
        int col = d2*8 + 2*qt;
        o0[col]     = acc_o[d2][0] * inv0;
        o0[col + 1] = acc_o[d2][1] * inv0;
        o1[col]     = acc_o[d2][2] * inv1;
        o1[col + 1] = acc_o[d2][3] * inv1;
    }
}

// ---------------- router ----------------
__global__ void gate_kernel(const float* __restrict__ gate_w) {
    int s = blockIdx.x;
    __shared__ float xrow[H];
    __shared__ float gates[NE];
    for (int i = threadIdx.x; i < H; i += blockDim.x) xrow[i] = g_x2[(long long)s * H + i];
    __syncthreads();
    int e = threadIdx.x >> 2, p = threadIdx.x & 3;
    float part = 0.f;
    const float* wrow = gate_w + (long long)e * H;
    for (int i = p * 192; i < (p + 1) * 192; i++) part += xrow[i] * wrow[i];
    part += __shfl_down_sync(0xffffffffu, part, 2);
    part += __shfl_down_sync(0xffffffffu, part, 1);
    if (p == 0) gates[e] = part;
    __syncthreads();
    if (threadIdx.x == 0) {
        float mx = -1e30f;
        for (int i = 0; i < NE; i++) mx = fmaxf(mx, gates[i]);
        float sum = 0.f;
        for (int i = 0; i < NE; i++) { float v = expf(gates[i] - mx); gates[i] = v; sum += v; }
        float inv = 1.f / sum;
        for (int i = 0; i < NE; i++) gates[i] *= inv;
        unsigned long long used = 0ull;
        float tsum = 0.f;
        int idxs[TOPK]; float vals[TOPK];
        for (int k = 0; k < TOPK; k++) {
            float bv = -1.f; int bi = 0;
            for (int i = 0; i < NE; i++) {
                if ((used >> i) & 1ull) continue;
                if (gates[i] > bv) { bv = gates[i]; bi = i; }
            }
            used |= 1ull << bi;
            idxs[k] = bi; vals[k] = bv; tsum += bv;
        }
        tsum = fmaxf(tsum, F32_EPS);
        for (int k = 0; k < TOPK; k++) {
            g_topi[s * TOPK + k] = idxs[k];
            g_topw[s * TOPK + k] = vals[k] / tsum;
        }
    }
}

// ---------------- capacity slot assignment ----------------
__global__ void slot_kernel() {
    __shared__ int ti[S * TOPK];
    __shared__ int cntk[TOPK][NE];
    for (int i = threadIdx.x; i < S * TOPK; i += 512) ti[i] = g_topi[i];
    __syncthreads();
    int k = threadIdx.x >> 6;
    int e = threadIdx.x & 63;
    int c = 0;
    for (int s = 0; s < S; s++)
        if (ti[s * TOPK + k] == e) { g_slot[s * TOPK + k] = c; c++; }
    cntk[k][e] = c;
    __syncthreads();
    int off = 0;
    for (int kk = 0; kk < k; kk++) off += cntk[kk][e];
    if (k == TOPK - 1) g_cnt[e] = min(off + c, CAP);
    for (int s = 0; s < S; s++) {
        if (ti[s * TOPK + k] == e) {
            int sl = g_slot[s * TOPK + k] + off;
            if (sl < CAP) { g_slot[s * TOPK + k] = sl; g_tok[e * CAP + sl] = s; }
            else g_slot[s * TOPK + k] = -1;
        }
    }
}

// ---------------- gather ----------------
__global__ void gather_kernel() {
    int e = blockIdx.y, c = blockIdx.x;
    float4* dst = (float4*)(g_xd + ((long long)e * CAP + c) * H);
    if (c < g_cnt[e]) {
        int s = g_tok[e * CAP + c];
        const float4* src = (const float4*)(g_x2 + (long long)s * H);
        for (int i = threadIdx.x; i < H / 4; i += blockDim.x) dst[i] = src[i];
    } else {
        float4 z = make_float4(0.f, 0.f, 0.f, 0.f);
        for (int i = threadIdx.x; i < H / 4; i += blockDim.x) dst[i] = z;
    }
}

// ---------------- combine ----------------
__global__ void combine_kernel(float* __restrict__ out) {
    int s = blockIdx.x;
    __shared__ int ee[TOPK]; __shared__ int sl[TOPK]; __shared__ float ww[TOPK];
    if (threadIdx.x < TOPK) {
        ee[threadIdx.x] = g_topi[s * TOPK + threadIdx.x];
        sl[threadIdx.x] = g_slot[s * TOPK + threadIdx.x];
        ww[threadIdx.x] = g_topw[s * TOPK + threadIdx.x];
    }
    __syncthreads();
    for (int m = threadIdx.x; m < H; m += blockDim.x) {
        float v = g_hidden[(long long)s * H + m] + g_shared[(long long)s * H + m];
#pragma unroll
        for (int k = 0; k < TOPK; k++)
            if (sl[k] >= 0)
                v += ww[k] * g_eout[((long long)ee[k] * CAP + sl[k]) * H + m];
        out[(long long)s * H + m] = v;
    }
}

// ---------------- launch ----------------
extern "C" void kernel_launch(void* const* d_in, const int* in_sizes, int n_in,
                              void* d_out, int out_size) {
    const float* hs    = (const float*)d_in[0];
    const float* cosb  = (const float*)d_in[1];
    const float* sinb  = (const float*)d_in[2];
    const float* iln   = (const float*)d_in[3];
    const float* pln   = (const float*)d_in[4];
    const float* qkvw  = (const float*)d_in[5];
    const float* ow    = (const float*)d_in[6];
    const float* qlw   = (const float*)d_in[7];
    const float* klw   = (const float*)d_in[8];
    const float* gatew = (const float*)d_in[9];
    const float* sguw  = (const float*)d_in[10];
    const float* sdw   = (const float*)d_in[11];
    const float* eguw  = (const float*)d_in[12];
    const float* edw   = (const float*)d_in[13];
    float* out = (float*)d_out;

    void *px1, *pqkv, *pattn, *phid, *px2, *pact, *pshared, *pxd, *peact, *peout, *pcnt;
    cudaGetSymbolAddress(&px1, g_x1);
    cudaGetSymbolAddress(&pqkv, g_qkv);
    cudaGetSymbolAddress(&pattn, g_attn);
    cudaGetSymbolAddress(&phid, g_hidden);
    cudaGetSymbolAddress(&px2, g_x2);
    cudaGetSymbolAddress(&pact, g_act);
    cudaGetSymbolAddress(&pshared, g_shared);
    cudaGetSymbolAddress(&pxd, g_xd);
    cudaGetSymbolAddress(&peact, g_eact);
    cudaGetSymbolAddress(&peout, g_eout);
    cudaGetSymbolAddress(&pcnt, g_cnt);

    cudaFuncSetAttribute(tc_gemm<256,0>, cudaFuncAttributeMaxDynamicSharedMemorySize, TC_SMEM_BYTES(256));
    cudaFuncSetAttribute(tc_gemm<256,2>, cudaFuncAttributeMaxDynamicSharedMemorySize, TC_SMEM_BYTES(256));
    cudaFuncSetAttribute(tc_gemm<128,0>, cudaFuncAttributeMaxDynamicSharedMemorySize, TC_SMEM_BYTES(128));
    cudaFuncSetAttribute(tc_gemm<128,1>, cudaFuncAttributeMaxDynamicSharedMemorySize, TC_SMEM_BYTES(128));

    // 1) input RMSNorm
    rmsnorm_kernel<<<S, 256>>>(hs, iln, (float*)px1);
    // 2) QKV projection
    tc_gemm<256,0><<<dim3(QKV_N/256, S/128, 1), 256, TC_SMEM_BYTES(256)>>>(
        (const float*)px1, qkvw, nullptr, (float*)pqkv, S, QKV_N, H, 0, 0, 0, nullptr);
    // 3) RoPE + q/k norm
    rope_norm_kernel<<<dim3(32, S), 64>>>(cosb, sinb, qlw, klw);
    // 4) attention
    attn_kernel<<<dim3(16, 16), 128>>>();
    // 5) O projection + residual
    tc_gemm<128,1><<<dim3(H/128, S/128, 1), 256, TC_SMEM_BYTES(128)>>>(
        (const float*)pattn, ow, hs, (float*)phid, S, H, HQ, 0, 0, 0, nullptr);
    // 6) post RMSNorm
    rmsnorm_kernel<<<S, 256>>>((const float*)phid, pln, (float*)px2);
    // 7) shared MLP: fused gu+SwiGLU -> act, then down-proj
    tc_gemm<256,2><<<dim3(FF/128, S/128, 1), 256, TC_SMEM_BYTES(256)>>>(
        (const float*)px2, sguw, nullptr, (float*)pact, S, FF, H, 0, 0, 0, nullptr);
    tc_gemm<128,0><<<dim3(H/128, S/128, 1), 256, TC_SMEM_BYTES(128)>>>(
        (const float*)pact, sdw, nullptr, (float*)pshared, S, H, FF, 0, 0, 0, nullptr);
    // 8) router + dispatch
    gate_kernel<<<S, 256>>>(gatew);
    slot_kernel<<<1, 512>>>();
    gather_kernel<<<dim3(CAP, NE), 192>>>();
    // 9) expert MLPs: fused gu+SwiGLU -> eact, then down-proj
    tc_gemm<256,2><<<dim3(FF/128, CAP/128, NE), 256, TC_SMEM_BYTES(256)>>>(
        (const float*)pxd, eguw, nullptr, (float*)peact, CAP, FF, H,
        (long long)CAP * H, (long long)2*FF * H, (long long)CAP * FF, (const int*)pcnt);
    tc_gemm<128,0><<<dim3(H/128, CAP/128, NE), 256, TC_SMEM_BYTES(128)>>>(
        (const float*)peact, edw, nullptr, (float*)peout, CAP, H, FF,
        (long long)CAP * FF, (long long)H * FF, (long long)CAP * H, (const int*)pcnt);
    // 10) combine
    combine_kernel<<<S, 256>>>(out);

    (void)in_sizes; (void)n_in; (void)out_size;
}

// round 12
// speedup vs baseline: 1.0852x; 1.0852x over previous
#include <cuda_runtime.h>
#include <math.h>

#define S 1024
#define H 768
#define NHEADS 16
#define KVH 8
#define D 64
#define HQ 1024
#define QKV_N 2048
#define NE 64
#define TOPK 8
#define FF 3072
#define CAP 256
#define RMS_EPS 1e-6f
#define F32_EPS 1.1920929e-07f

#ifdef __CUDA_ARCH_FEAT_SM103_ALL
#define HAS_TC 1
#else
#define HAS_TC 0
#endif

// ---------------- scratch ----------------
__device__ float g_x1[S*H];
__device__ float g_qkv[S*QKV_N];
__device__ float g_q[NHEADS*S*D];
__device__ float g_k[KVH*S*D];
__device__ float g_v[KVH*S*D];
__device__ float g_attn[S*HQ];
__device__ float g_hidden[S*H];
__device__ float g_x2[S*H];
__device__ float g_act[S*FF];
__device__ float g_shared[S*H];
__device__ int   g_topi[S*TOPK];
__device__ float g_topw[S*TOPK];
__device__ int   g_slot[S*TOPK];
__device__ int   g_cnt[NE];
__device__ int   g_tok[NE*CAP];
__device__ float g_xd[NE*CAP*H];
__device__ float g_eact[NE*CAP*FF];
__device__ float g_eout[NE*CAP*H];

// ---------------- helpers ----------------
__device__ __forceinline__ float to_tf32(float x) {
    unsigned u;
    asm("cvt.rna.tf32.f32 %0, %1;" : "=r"(u) : "f"(x));
    return __uint_as_float(u);
}
__device__ __forceinline__ float4 cvt4(float4 v) {
    return make_float4(to_tf32(v.x), to_tf32(v.y), to_tf32(v.z), to_tf32(v.w));
}
__device__ __forceinline__ unsigned smem_to_u32(const void* p) {
    unsigned addr;
    asm("{ .reg .u64 t;\n\t"
        "cvta.to.shared.u64 t, %1;\n\t"
        "cvt.u32.u64 %0, t; }"
        : "=r"(addr) : "l"(p));
    return addr;
}
__device__ __forceinline__ void mma_tf32(float* d, const float* a, const float* b) {
    asm volatile(
        "mma.sync.aligned.m16n8k8.row.col.f32.tf32.tf32.f32\n\t"
        "{%0,%1,%2,%3},\n\t"
        "{%4,%5,%6,%7},\n\t"
        "{%8,%9},\n\t"
        "{%0,%1,%2,%3};"
        : "+f"(d[0]), "+f"(d[1]), "+f"(d[2]), "+f"(d[3])
        : "r"(__float_as_uint(a[0])), "r"(__float_as_uint(a[1])),
          "r"(__float_as_uint(a[2])), "r"(__float_as_uint(a[3])),
          "r"(__float_as_uint(b[0])), "r"(__float_as_uint(b[1])));
}
__device__ __forceinline__ float silu_mul(float g, float u) {
    return g * (u / (1.f + __expf(-u)));
}

#define SMEM_SWIZZLE_128B(o) ((o) ^ (((o) >> 3) & 0x70))

#if HAS_TC
__device__ __forceinline__ unsigned long long make_desc(unsigned addr) {
    unsigned long long d = 0;
    d |= (unsigned long long)(addr >> 4) & 0x3FFFull;
    d |= 1ull << 16;
    d |= 64ull << 32;
    d |= 1ull << 46;
    d |= 2ull << 61;
    return d;
}
__device__ __forceinline__ void mbar_init(unsigned mbar, unsigned cnt) {
    asm volatile("mbarrier.init.shared.b64 [%0], %1;" :: "r"(mbar), "r"(cnt) : "memory");
}
__device__ __forceinline__ void mbar_wait(unsigned mbar, unsigned parity) {
    unsigned done;
    asm volatile(
        "{ .reg .pred p;\n\t"
        "mbarrier.try_wait.parity.acquire.cta.shared::cta.b64 p, [%1], %2;\n\t"
        "selp.b32 %0, 1, 0, p; }"
        : "=r"(done) : "r"(mbar), "r"(parity) : "memory");
    if (!done) {
        asm volatile(
            "{ .reg .pred p;\n\t"
            "LW%=:\n\t"
            "mbarrier.try_wait.parity.acquire.cta.shared::cta.b64 p, [%0], %1, 0x989680;\n\t"
            "@p bra.uni LD%=;\n\t"
            "bra.uni LW%=;\n\t"
            "LD%=: }"
            :: "r"(mbar), "r"(parity) : "memory");
    }
}
__device__ __forceinline__ void tc_alloc(unsigned smem_dst, unsigned ncols) {
    asm volatile(
        "tcgen05.alloc.cta_group::1.sync.aligned.shared::cta.b32 [%0], %1;"
        :: "r"(smem_dst), "r"(ncols) : "memory");
}
__device__ __forceinline__ void tc_dealloc(unsigned taddr, unsigned ncols) {
    asm volatile(
        "tcgen05.dealloc.cta_group::1.sync.aligned.b32 %0, %1;"
        :: "r"(taddr), "r"(ncols));
}
__device__ __forceinline__ void tc_relinquish() {
    asm volatile("tcgen05.relinquish_alloc_permit.cta_group::1.sync.aligned;");
}
__device__ __forceinline__ void tc_commit(unsigned mbar) {
    asm volatile(
        "tcgen05.commit.cta_group::1.mbarrier::arrive::one.shared::cluster.b64 [%0];"
        :: "r"(mbar) : "memory");
}
__device__ __forceinline__ void tc_fence_after() {
    asm volatile("tcgen05.fence::after_thread_sync;" ::: "memory");
}
__device__ __forceinline__ void tc_wait_ld() {
    asm volatile("tcgen05.wait::ld.sync.aligned;" ::: "memory");
}
__device__ __forceinline__ void fence_async() {
    asm volatile("fence.proxy.async.shared::cta;" ::: "memory");
}
__device__ __forceinline__ void tc_ld_x8(unsigned* r, unsigned taddr) {
    asm volatile(
        "tcgen05.ld.sync.aligned.32x32b.x8.b32\n\t"
        "{%0, %1, %2, %3, %4, %5, %6, %7}, [%8];"
        : "=r"(r[0]), "=r"(r[1]), "=r"(r[2]), "=r"(r[3]),
          "=r"(r[4]), "=r"(r[5]), "=r"(r[6]), "=r"(r[7])
        : "r"(taddr));
}
__device__ __forceinline__ void tc_mma_tf32(
    unsigned dtm, unsigned long long ad, unsigned long long bd,
    unsigned idesc, unsigned en)
{
    asm volatile(
        "{ .reg .pred p;\n\t"
        "setp.ne.u32 p, %4, 0;\n\t"
        "tcgen05.mma.cta_group::1.kind::tf32 [%0], %1, %2, %3, p; }"
        :: "r"(dtm), "l"(ad), "l"(bd), "r"(idesc), "r"(en)
        : "memory");
}
#endif  // HAS_TC

// ---------------- dual-path GEMM (tf32 tcgen05, 128-row tiles, 2 CTAs/SM) ----------------
// MODE 0: C = A*B^T.  MODE 1: C = A*B^T + Res.
// MODE 2 (SwiGLU): B-tile = 128 gate rows ++ 128 up rows; C = gate*silu(up). (NT=256)
#define TC_SMEM_BYTES(NT) (1024 + 2*16384 + 2*(NT)*128)

template <int NT, int MODE>
__global__ void __launch_bounds__(256) tc_gemm(
    const float* __restrict__ A, const float* __restrict__ B,
    const float* __restrict__ Res, float* __restrict__ C,
    int M, int N, int K,
    long long sA, long long sB, long long sC, const int* __restrict__ rowcnt)
{
    int bz = blockIdx.z;
    int row0 = blockIdx.y * 128;
    int col0 = blockIdx.x * ((MODE == 2) ? NT/2 : NT);
    if (rowcnt && row0 >= rowcnt[bz]) return;
    const float* Ab = A + (long long)bz * sA;
    const float* Bb = B + (long long)bz * sB;
    float* Cb = C + (long long)bz * sC;
    extern __shared__ char smem[];
    int tid = threadIdx.x, wid = tid >> 5, lane = tid & 31;

#if HAS_TC
    unsigned smem_base = smem_to_u32(smem);
    const unsigned IDESC = (1u<<4) | (2u<<7) | (2u<<10)
                         | ((unsigned)(NT>>3)<<17) | (8u<<24);
    if (wid == 0) { tc_alloc(smem_base, NT); tc_relinquish(); }
    if (tid == 0) { mbar_init(smem_base + 16, 1); mbar_init(smem_base + 24, 1); }
    __syncthreads();
    unsigned tmem_base = *(volatile unsigned*)smem;

    const int ABUF = 1024;
    const int BBUF = 1024 + 32768;
    const int BSZ = NT * 128;

    float4 av[4], bv[NT/32];
    auto load_chunk = [&](int ci) {
        int k0 = ci << 5;
#pragma unroll
        for (int it = 0; it < 4; it++) {
            int idx = it * 256 + tid, r = idx >> 3, c = (idx & 7) * 4;
            av[it] = *(const float4*)&Ab[(long long)(row0 + r) * K + k0 + c];
        }
#pragma unroll
        for (int it = 0; it < NT/32; it++) {
            int idx = it * 256 + tid, r = idx >> 3, c = (idx & 7) * 4;
            int brow = (MODE == 2) ? ((r < NT/2) ? (col0 + r) : (FF + col0 + r - NT/2))
                                   : (col0 + r);
            bv[it] = *(const float4*)&Bb[(long long)brow * K + k0 + c];
        }
    };

    int nc = K >> 5;
    load_chunk(0);
    for (int i = 0; i < nc; i++) {
        int buf = i & 1;
        if (i >= 2) mbar_wait(smem_base + 16 + 8*buf, ((i-2)>>1) & 1);
        char* As = smem + ABUF + buf * 16384;
        char* Bs = smem + BBUF + buf * BSZ;
#pragma unroll
        for (int it = 0; it < 4; it++) {
            int idx = it * 256 + tid, r = idx >> 3, c = (idx & 7) * 4;
            unsigned off = (unsigned)(r * 128 + c * 4);
            *(float4*)(As + SMEM_SWIZZLE_128B(off)) = cvt4(av[it]);
        }
#pragma unroll
        for (int it = 0; it < NT/32; it++) {
            int idx = it * 256 + tid, r = idx >> 3, c = (idx & 7) * 4;
            unsigned off = (unsigned)(r * 128 + c * 4);
            *(float4*)(Bs + SMEM_SWIZZLE_128B(off)) = cvt4(bv[it]);
        }
        if (i + 1 < nc) load_chunk(i + 1);
        fence_async();
        __syncthreads();
        if (tid == 0) {
            unsigned long long ad = make_desc(smem_base + ABUF + buf*16384);
            unsigned long long bd = make_desc(smem_base + BBUF + buf*BSZ);
#pragma unroll
            for (int sub = 0; sub < 4; sub++)
                tc_mma_tf32(tmem_base, ad + sub*2, bd + sub*2, IDESC,
                            (i > 0 || sub > 0) ? 1u : 0u);
            tc_commit(smem_base + 16 + 8*buf);
        }
    }
    mbar_wait(smem_base + 16 + 8*((nc-2)&1), ((nc-2)>>1) & 1);
    mbar_wait(smem_base + 16 + 8*((nc-1)&1), ((nc-1)>>1) & 1);
    tc_fence_after();

    long long r = row0 + (wid & 3) * 32 + lane;
    if (MODE == 2) {
#pragma unroll
        for (int cc = 0; cc < 2; cc++) {
            int gc = (wid >> 2) * 2 + cc;
            unsigned gr[32], ur[32];
#pragma unroll
            for (int q = 0; q < 4; q++)
                tc_ld_x8(gr + q*8, tmem_base + gc*32 + q*8);
#pragma unroll
            for (int q = 0; q < 4; q++)
                tc_ld_x8(ur + q*8, tmem_base + 128 + gc*32 + q*8);
            tc_wait_ld();
            long long cbase = col0 + gc * 32;
            float vals[32];
#pragma unroll
            for (int j = 0; j < 32; j++)
                vals[j] = silu_mul(__uint_as_float(gr[j]), __uint_as_float(ur[j]));
#pragma unroll
            for (int j = 0; j < 32; j += 4)
                *(float4*)&Cb[r * N + cbase + j] =
                    make_float4(vals[j], vals[j+1], vals[j+2], vals[j+3]);
        }
    } else {
        const int CPW = NT / 64;
#pragma unroll
        for (int cc = 0; cc < CPW; cc++) {
            int chunk = (wid >> 2) * CPW + cc;
            unsigned regs[32];
#pragma unroll
            for (int q = 0; q < 4; q++)
                tc_ld_x8(regs + q*8, tmem_base + chunk*32 + q*8);
            tc_wait_ld();
            long long cbase = col0 + chunk * 32;
            float vals[32];
#pragma unroll
            for (int j = 0; j < 32; j++) vals[j] = __uint_as_float(regs[j]);
            if (MODE == 1) {
#pragma unroll
                for (int j = 0; j < 32; j++) vals[j] += Res[r * N + cbase + j];
            }
#pragma unroll
            for (int j = 0; j < 32; j += 4)
                *(float4*)&Cb[r * N + cbase + j] =
                    make_float4(vals[j], vals[j+1], vals[j+2], vals[j+3]);
        }
    }
    __syncthreads();
    if (wid == 0) tc_dealloc(tmem_base, NT);
#else
    // -------- fallback: mma.sync TF32 path (128x128 subtiles) --------
    int warp_m = wid >> 2, warp_n = wid & 3;
    float (*As)[8][4][32]  = (float(*)[8][4][32])smem;
    float (*Bs)[16][2][32] = (float(*)[16][2][32])(smem + 16384);
    float gate_st[4][4][4];
#pragma unroll
    for (int cb = 0; cb < NT/128; cb++) {
        const float* Ar = Ab + (long long)row0 * K;
        long long brow0 = (MODE == 2) ? ((cb == 0) ? col0 : (FF + col0))
                                      : (col0 + cb*128);
        const float* Br = Bb + brow0 * K;
        float acc[4][4][4];
#pragma unroll
        for (int mi = 0; mi < 4; mi++)
#pragma unroll
            for (int ni = 0; ni < 4; ni++)
#pragma unroll
                for (int rr = 0; rr < 4; rr++) acc[mi][ni][rr] = 0.f;
        float4 areg[4], breg[4];
#pragma unroll
        for (int it = 0; it < 4; it++) {
            int idx = it * 256 + tid, r = idx >> 3, c4 = (idx & 7) * 4;
            areg[it] = *(const float4*)&Ar[(long long)r * K + c4];
            breg[it] = *(const float4*)&Br[(long long)r * K + c4];
        }
        for (int k0 = 0; k0 < K; k0 += 32) {
#pragma unroll
            for (int it = 0; it < 4; it++) {
                int idx = it * 256 + tid, r = idx >> 3, k4 = (idx & 7) * 4;
                int kstep = k4 >> 3, khi = (k4 & 7) >> 2;
                int mtile = r >> 4, rr2 = r & 15, gA = rr2 & 7, hi = rr2 >> 3;
                *(float4*)&As[kstep][mtile][hi + 2*khi][gA * 4] = cvt4(areg[it]);
                int ntile = r >> 3, gB = r & 7;
                *(float4*)&Bs[kstep][ntile][khi][gB * 4] = cvt4(breg[it]);
            }
            __syncthreads();
            if (k0 + 32 < K) {
#pragma unroll
                for (int it = 0; it < 4; it++) {
                    int idx = it * 256 + tid, r = idx >> 3, c4 = (idx & 7) * 4;
                    areg[it] = *(const float4*)&Ar[(long long)r * K + k0 + 32 + c4];
                    breg[it] = *(const float4*)&Br[(long long)r * K + k0 + 32 + c4];
                }
            }
#pragma unroll
            for (int kstep = 0; kstep < 4; kstep++) {
                float a[4][4], b[4][2];
#pragma unroll
                for (int mi = 0; mi < 4; mi++)
#pragma unroll
                    for (int rr = 0; rr < 4; rr++)
                        a[mi][rr] = As[kstep][warp_m * 4 + mi][rr][lane];
#pragma unroll
                for (int ni = 0; ni < 4; ni++)
#pragma unroll
                    for (int rr = 0; rr < 2; rr++)
                        b[ni][rr] = Bs[kstep][warp_n * 4 + ni][rr][lane];
#pragma unroll
                for (int mi = 0; mi < 4; mi++)
#pragma unroll
                    for (int ni = 0; ni < 4; ni++)
                        mma_tf32(acc[mi][ni], a[mi], b[ni]);
            }
            __syncthreads();
        }
        if (MODE == 2 && cb == 0) {
#pragma unroll
            for (int mi = 0; mi < 4; mi++)
#pragma unroll
                for (int ni = 0; ni < 4; ni++)
#pragma unroll
                    for (int rr = 0; rr < 4; rr++)
                        gate_st[mi][ni][rr] = acc[mi][ni][rr];
            continue;
        }
        int g = lane >> 2, c = lane & 3;
#pragma unroll
        for (int mi = 0; mi < 4; mi++) {
#pragma unroll
            for (int ni = 0; ni < 4; ni++) {
                long long row = row0 + warp_m * 64 + mi * 16 + g;
                long long col = col0 + ((MODE == 2) ? 0 : cb*128)
                              + warp_n * 32 + ni * 8 + c * 2;
                float v0, v1, v2, v3;
                if (MODE == 2) {
                    v0 = silu_mul(gate_st[mi][ni][0], acc[mi][ni][0]);
                    v1 = silu_mul(gate_st[mi][ni][1], acc[mi][ni][1]);
                    v2 = silu_mul(gate_st[mi][ni][2], acc[mi][ni][2]);
                    v3 = silu_mul(gate_st[mi][ni][3], acc[mi][ni][3]);
                } else {
                    v0 = acc[mi][ni][0]; v1 = acc[mi][ni][1];
                    v2 = acc[mi][ni][2]; v3 = acc[mi][ni][3];
                    if (MODE == 1) {
                        v0 += Res[row * N + col];       v1 += Res[row * N + col + 1];
                        v2 += Res[(row + 8) * N + col]; v3 += Res[(row + 8) * N + col + 1];
                    }
                }
                *(float2*)&Cb[row * N + col]       = make_float2(v0, v1);
                *(float2*)&Cb[(row + 8) * N + col] = make_float2(v2, v3);
            }
        }
    }
#endif
}

// ---------------- RMSNorm over H ----------------
__global__ void rmsnorm_kernel(const float* __restrict__ in, const float* __restrict__ w,
                               float* __restrict__ out) {
    int s = blockIdx.x;
    const float* row = in + (long long)s * H;
    __shared__ float red[8];
    float ss = 0.f;
    for (int i = threadIdx.x; i < H; i += blockDim.x) { float v = row[i]; ss += v * v; }
    for (int o = 16; o; o >>= 1) ss += __shfl_down_sync(0xffffffffu, ss, o);
    if ((threadIdx.x & 31) == 0) red[threadIdx.x >> 5] = ss;
    __syncthreads();
    if (threadIdx.x == 0) {
        float t = 0.f;
        for (int i = 0; i < (int)(blockDim.x >> 5); i++) t += red[i];
        red[0] = t;
    }
    __syncthreads();
    float inv = rsqrtf(red[0] / (float)H + RMS_EPS);
    for (int i = threadIdx.x; i < H; i += blockDim.x)
        out[(long long)s * H + i] = w[i] * (row[i] * inv);
}

// ---------------- RoPE + per-head RMSNorm, split qkv ----------------
__global__ void rope_norm_kernel(const float* __restrict__ cosb, const float* __restrict__ sinb,
                                 const float* __restrict__ qw, const float* __restrict__ kw) {
    int u = blockIdx.x, s = blockIdx.y, d = threadIdx.x;
    if (u >= 24) {
        int kvh = u - 24;
        g_v[((long long)kvh * S + s) * D + d] = g_qkv[(long long)s * QKV_N + (kvh * 4 + 3) * D + d];
        return;
    }
    int n; const float* w; float* dst;
    if (u < 16) {
        int kvh = u >> 1, j = u & 1;
        n = (kvh * 4 + j) * D + d; w = qw;
        dst = &g_q[((long long)u * S + s) * D + d];
    } else {
        int kvh = u - 16;
        n = (kvh * 4 + 2) * D + d; w = kw;
        dst = &g_k[((long long)kvh * S + s) * D + d];
    }
    float val = g_qkv[(long long)s * QKV_N + n];
    float other = (d < 32) ? -g_qkv[(long long)s * QKV_N + n + 32]
                           :  g_qkv[(long long)s * QKV_N + n - 32];
    float r = val * cosb[(long long)s * D + d] + other * sinb[(long long)s * D + d];
    float ss = r * r;
    for (int o = 16; o; o >>= 1) ss += __shfl_xor_sync(0xffffffffu, ss, o);
    __shared__ float sh[2];
    if ((d & 31) == 0) sh[d >> 5] = ss;
    __syncthreads();
    float inv = rsqrtf((sh[0] + sh[1]) / (float)D + RMS_EPS);
    *dst = w[d] * (r * inv);
}

// ---------------- tensor-core causal flash attention (2 heads/CTA, shared KV) ----------------
// CTA = (qb, kvh). Warps 0-3 -> head 2*kvh, warps 4-7 -> head 2*kvh+1.
// K/V tiles staged once, shared by both halves (GQA). Per-half math identical to R7.
__global__ void __launch_bounds__(256) attn_kernel() {
    int qb = gridDim.x - 1 - blockIdx.x;
    int kvh = blockIdx.y;
    int tid = threadIdx.x, wid = tid >> 5, lane = tid & 31;
    int half = wid >> 2, wid4 = wid & 3;
    int h = 2 * kvh + half;
    int htid = tid & 127;
    int g = lane >> 2, qt = lane & 3;

    __shared__ float Qs[2][64][64];
    __shared__ float Bqk[8][4][2][32];
    __shared__ float Bpv[4][8][2][32];

    const float* qbase = g_q + ((long long)h * S + qb * 64) * D;
    for (int i = htid; i < 64 * 64; i += 128)
        Qs[half][i >> 6][i & 63] = to_tf32(qbase[i] * 0.125f);
    __syncthreads();

    float a_q[8][4];
#pragma unroll
    for (int ks = 0; ks < 8; ks++) {
        a_q[ks][0] = Qs[half][wid4*16 + g    ][ks*8 + qt];
        a_q[ks][1] = Qs[half][wid4*16 + g + 8][ks*8 + qt];
        a_q[ks][2] = Qs[half][wid4*16 + g    ][ks*8 + 4 + qt];
        a_q[ks][3] = Qs[half][wid4*16 + g + 8][ks*8 + 4 + qt];
    }

    float acc_o[8][4];
#pragma unroll
    for (int d2 = 0; d2 < 8; d2++)
#pragma unroll
        for (int r = 0; r < 4; r++) acc_o[d2][r] = 0.f;

    float m0 = -1e30f, m1 = -1e30f, l0 = 0.f, l1 = 0.f;
    int gq0 = qb*64 + wid4*16 + g;
    int gq1 = gq0 + 8;
    int nkt = 2*qb + 2;

    for (int kt = 0; kt < nkt; kt++) {
        int kbase = kt * 32;
        __syncthreads();
        // K/V staged once for both heads (same kvh)
        const float* kptr = g_k + ((long long)kvh * S + kbase) * D;
        for (int i = tid; i < 512; i += 256) {
            int r = i >> 4, c4 = (i & 15) * 4;
            float4 v = cvt4(*(const float4*)&kptr[r*64 + c4]);
            *(float4*)&Bqk[c4 >> 3][r >> 3][(c4 >> 2) & 1][(r & 7) * 4] = v;
        }
        const float* vptr = g_v + ((long long)kvh * S + kbase) * D;
        for (int i = tid; i < 512; i += 256) {
            int r = i >> 4, c4 = (i & 15) * 4;
            float4 v = cvt4(*(const float4*)&vptr[r*64 + c4]);
            int ks = r >> 3, reg = (r >> 2) & 1;
            int nt = c4 >> 3, lb = (c4 & 7) * 4 + (r & 3);
            Bpv[ks][nt][reg][lb]      = v.x;
            Bpv[ks][nt][reg][lb + 4]  = v.y;
            Bpv[ks][nt][reg][lb + 8]  = v.z;
            Bpv[ks][nt][reg][lb + 12] = v.w;
        }
        __syncthreads();

        float sacc[4][4];
#pragma unroll
        for (int nt = 0; nt < 4; nt++)
#pragma unroll
            for (int r = 0; r < 4; r++) sacc[nt][r] = 0.f;
#pragma unroll
        for (int nt = 0; nt < 4; nt++)
#pragma unroll
            for (int ks = 0; ks < 8; ks++) {
                float b[2] = { Bqk[ks][nt][0][lane], Bqk[ks][nt][1][lane] };
                mma_tf32(sacc[nt], a_q[ks], b);
            }

        float mn0 = m0, mn1 = m1;
#pragma unroll
        for (int nt = 0; nt < 4; nt++) {
            int col = kbase + nt*8 + 2*qt;
            if (col     > gq0) sacc[nt][0] = -1e30f;
            if (col + 1 > gq0) sacc[nt][1] = -1e30f;
            if (col     > gq1) sacc[nt][2] = -1e30f;
            if (col + 1 > gq1) sacc[nt][3] = -1e30f;
            mn0 = fmaxf(mn0, fmaxf(sacc[nt][0], sacc[nt][1]));
            mn1 = fmaxf(mn1, fmaxf(sacc[nt][2], sacc[nt][3]));
        }
        mn0 = fmaxf(mn0, __shfl_xor_sync(0xffffffffu, mn0, 1));
        mn0 = fmaxf(mn0, __shfl_xor_sync(0xffffffffu, mn0, 2));
        mn1 = fmaxf(mn1, __shfl_xor_sync(0xffffffffu, mn1, 1));
        mn1 = fmaxf(mn1, __shfl_xor_sync(0xffffffffu, mn1, 2));

        float al0 = __expf(m0 - mn0), al1 = __expf(m1 - mn1);
        float rs0 = 0.f, rs1 = 0.f;
#pragma unroll
        for (int nt = 0; nt < 4; nt++) {
            sacc[nt][0] = __expf(sacc[nt][0] - mn0);
            sacc[nt][1] = __expf(sacc[nt][1] - mn0);
            sacc[nt][2] = __expf(sacc[nt][2] - mn1);
            sacc[nt][3] = __expf(sacc[nt][3] - mn1);
            rs0 += sacc[nt][0] + sacc[nt][1];
            rs1 += sacc[nt][2] + sacc[nt][3];
        }
        rs0 += __shfl_xor_sync(0xffffffffu, rs0, 1);
        rs0 += __shfl_xor_sync(0xffffffffu, rs0, 2);
        rs1 += __shfl_xor_sync(0xffffffffu, rs1, 1);
        rs1 += __shfl_xor_sync(0xffffffffu, rs1, 2);
        l0 = l0 * al0 + rs0;
        l1 = l1 * al1 + rs1;
        m0 = mn0; m1 = mn1;

#pragma unroll
        for (int d2 = 0; d2 < 8; d2++) {
            acc_o[d2][0] *= al0; acc_o[d2][1] *= al0;
            acc_o[d2][2] *= al1; acc_o[d2][3] *= al1;
        }

        float a_p[4][4];
        int base = lane & ~3;
        int s1 = base + (qt >> 1);
        int s2 = base + 2 + (qt >> 1);
        bool odd = (qt & 1) != 0;
#pragma unroll
        for (int ks = 0; ks < 4; ks++) {
            float u0 = __shfl_sync(0xffffffffu, sacc[ks][0], s1);
            float u1 = __shfl_sync(0xffffffffu, sacc[ks][1], s1);
            float u2 = __shfl_sync(0xffffffffu, sacc[ks][2], s1);
            float u3 = __shfl_sync(0xffffffffu, sacc[ks][3], s1);
            float w0 = __shfl_sync(0xffffffffu, sacc[ks][0], s2);
            float w1 = __shfl_sync(0xffffffffu, sacc[ks][1], s2);
            float w2 = __shfl_sync(0xffffffffu, sacc[ks][2], s2);
            float w3 = __shfl_sync(0xffffffffu, sacc[ks][3], s2);
            a_p[ks][0] = to_tf32(odd ? u1 : u0);
            a_p[ks][1] = to_tf32(odd ? u3 : u2);
            a_p[ks][2] = to_tf32(odd ? w1 : w0);
            a_p[ks][3] = to_tf32(odd ? w3 : w2);
        }

#pragma unroll
        for (int d2 = 0; d2 < 8; d2++)
#pragma unroll
            for (int ks = 0; ks < 4; ks++) {
                float b[2] = { Bpv[ks][d2][0][lane], Bpv[ks][d2][1][lane] };
                mma_tf32(acc_o[d2], a_p[ks], b);
            }
    }

    float inv0 = 1.f / l0, inv1 = 1.f / l1;
    float* o0 = g_attn + (long long)gq0 * HQ + h * D;
    float* o1 = g_attn + (long long)gq1 * HQ + h * D;
#pragma unroll
    for (int d2 = 0; d2 < 8; d2++) {
        int col = d2*8 + 2*qt;
        o0[col]     = acc_o[d2][0] * inv0;
        o0[col + 1] = acc_o[d2][1] * inv0;
        o1[col]     = acc_o[d2][2] * inv1;
        o1[col + 1] = acc_o[d2][3] * inv1;
    }
}

// ---------------- router ----------------
__global__ void gate_kernel(const float* __restrict__ gate_w) {
    int s = blockIdx.x;
    __shared__ float xrow[H];
    __shared__ float gates[NE];
    for (int i = threadIdx.x; i < H; i += blockDim.x) xrow[i] = g_x2[(long long)s * H + i];
    __syncthreads();
    int e = threadIdx.x >> 2, p = threadIdx.x & 3;
    float part = 0.f;
    const float* wrow = gate_w + (long long)e * H;
    for (int i = p * 192; i < (p + 1) * 192; i++) part += xrow[i] * wrow[i];
    part += __shfl_down_sync(0xffffffffu, part, 2);
    part += __shfl_down_sync(0xffffffffu, part, 1);
    if (p == 0) gates[e] = part;
    __syncthreads();
    if (threadIdx.x == 0) {
        float mx = -1e30f;
        for (int i = 0; i < NE; i++) mx = fmaxf(mx, gates[i]);
        float sum = 0.f;
        for (int i = 0; i < NE; i++) { float v = expf(gates[i] - mx); gates[i] = v; sum += v; }
        float inv = 1.f / sum;
        for (int i = 0; i < NE; i++) gates[i] *= inv;
        unsigned long long used = 0ull;
        float tsum = 0.f;
        int idxs[TOPK]; float vals[TOPK];
        for (int k = 0; k < TOPK; k++) {
            float bv = -1.f; int bi = 0;
            for (int i = 0; i < NE; i++) {
                if ((used >> i) & 1ull) continue;
                if (gates[i] > bv) { bv = gates[i]; bi = i; }
            }
            used |= 1ull << bi;
            idxs[k] = bi; vals[k] = bv; tsum += bv;
        }
        tsum = fmaxf(tsum, F32_EPS);
        for (int k = 0; k < TOPK; k++) {
            g_topi[s * TOPK + k] = idxs[k];
            g_topw[s * TOPK + k] = vals[k] / tsum;
        }
    }
}

// ---------------- capacity slot assignment ----------------
__global__ void slot_kernel() {
    __shared__ int ti[S * TOPK];
    __shared__ int cntk[TOPK][NE];
    for (int i = threadIdx.x; i < S * TOPK; i += 512) ti[i] = g_topi[i];
    __syncthreads();
    int k = threadIdx.x >> 6;
    int e = threadIdx.x & 63;
    int c = 0;
    for (int s = 0; s < S; s++)
        if (ti[s * TOPK + k] == e) { g_slot[s * TOPK + k] = c; c++; }
    cntk[k][e] = c;
    __syncthreads();
    int off = 0;
    for (int kk = 0; kk < k; kk++) off += cntk[kk][e];
    if (k == TOPK - 1) g_cnt[e] = min(off + c, CAP);
    for (int s = 0; s < S; s++) {
        if (ti[s * TOPK + k] == e) {
            int sl = g_slot[s * TOPK + k] + off;
            if (sl < CAP) { g_slot[s * TOPK + k] = sl; g_tok[e * CAP + sl] = s; }
            else g_slot[s * TOPK + k] = -1;
        }
    }
}

// ---------------- gather ----------------
__global__ void gather_kernel() {
    int e = blockIdx.y, c = blockIdx.x;
    float4* dst = (float4*)(g_xd + ((long long)e * CAP + c) * H);
    if (c < g_cnt[e]) {
        int s = g_tok[e * CAP + c];
        const float4* src = (const float4*)(g_x2 + (long long)s * H);
        for (int i = threadIdx.x; i < H / 4; i += blockDim.x) dst[i] = src[i];
    } else {
        float4 z = make_float4(0.f, 0.f, 0.f, 0.f);
        for (int i = threadIdx.x; i < H / 4; i += blockDim.x) dst[i] = z;
    }
}

// ---------------- combine ----------------
__global__ void combine_kernel(float* __restrict__ out) {
    int s = blockIdx.x;
    __shared__ int ee[TOPK]; __shared__ int sl[TOPK]; __shared__ float ww[TOPK];
    if (threadIdx.x < TOPK) {
        ee[threadIdx.x] = g_topi[s * TOPK + threadIdx.x];
        sl[threadIdx.x] = g_slot[s * TOPK + threadIdx.x];
        ww[threadIdx.x] = g_topw[s * TOPK + threadIdx.x];
    }
    __syncthreads();
    for (int m = threadIdx.x; m < H; m += blockDim.x) {
        float v = g_hidden[(long long)s * H + m] + g_shared[(long long)s * H + m];
#pragma unroll
        for (int k = 0; k < TOPK; k++)
            if (sl[k] >= 0)
                v += ww[k] * g_eout[((long long)ee[k] * CAP + sl[k]) * H + m];
        out[(long long)s * H + m] = v;
    }
}

// ---------------- launch ----------------
extern "C" void kernel_launch(void* const* d_in, const int* in_sizes, int n_in,
                              void* d_out, int out_size) {
    const float* hs    = (const float*)d_in[0];
    const float* cosb  = (const float*)d_in[1];
    const float* sinb  = (const float*)d_in[2];
    const float* iln   = (const float*)d_in[3];
    const float* pln   = (const float*)d_in[4];
    const float* qkvw  = (const float*)d_in[5];
    const float* ow    = (const float*)d_in[6];
    const float* qlw   = (const float*)d_in[7];
    const float* klw   = (const float*)d_in[8];
    const float* gatew = (const float*)d_in[9];
    const float* sguw  = (const float*)d_in[10];
    const float* sdw   = (const float*)d_in[11];
    const float* eguw  = (const float*)d_in[12];
    const float* edw   = (const float*)d_in[13];
    float* out = (float*)d_out;

    void *px1, *pqkv, *pattn, *phid, *px2, *pact, *pshared, *pxd, *peact, *peout, *pcnt;
    cudaGetSymbolAddress(&px1, g_x1);
    cudaGetSymbolAddress(&pqkv, g_qkv);
    cudaGetSymbolAddress(&pattn, g_attn);
    cudaGetSymbolAddress(&phid, g_hidden);
    cudaGetSymbolAddress(&px2, g_x2);
    cudaGetSymbolAddress(&pact, g_act);
    cudaGetSymbolAddress(&pshared, g_shared);
    cudaGetSymbolAddress(&pxd, g_xd);
    cudaGetSymbolAddress(&peact, g_eact);
    cudaGetSymbolAddress(&peout, g_eout);
    cudaGetSymbolAddress(&pcnt, g_cnt);

    cudaFuncSetAttribute(tc_gemm<256,0>, cudaFuncAttributeMaxDynamicSharedMemorySize, TC_SMEM_BYTES(256));
    cudaFuncSetAttribute(tc_gemm<256,2>, cudaFuncAttributeMaxDynamicSharedMemorySize, TC_SMEM_BYTES(256));
    cudaFuncSetAttribute(tc_gemm<128,0>, cudaFuncAttributeMaxDynamicSharedMemorySize, TC_SMEM_BYTES(128));
    cudaFuncSetAttribute(tc_gemm<128,1>, cudaFuncAttributeMaxDynamicSharedMemorySize, TC_SMEM_BYTES(128));

    // 1) input RMSNorm
    rmsnorm_kernel<<<S, 256>>>(hs, iln, (float*)px1);
    // 2) QKV projection
    tc_gemm<256,0><<<dim3(QKV_N/256, S/128, 1), 256, TC_SMEM_BYTES(256)>>>(
        (const float*)px1, qkvw, nullptr, (float*)pqkv, S, QKV_N, H, 0, 0, 0, nullptr);
    // 3) RoPE + q/k norm
    rope_norm_kernel<<<dim3(32, S), 64>>>(cosb, sinb, qlw, klw);
    // 4) attention (2 heads per CTA, shared KV)
    attn_kernel<<<dim3(16, KVH), 256>>>();
    // 5) O projection + residual
    tc_gemm<128,1><<<dim3(H/128, S/128, 1), 256, TC_SMEM_BYTES(128)>>>(
        (const float*)pattn, ow, hs, (float*)phid, S, H, HQ, 0, 0, 0, nullptr);
    // 6) post RMSNorm
    rmsnorm_kernel<<<S, 256>>>((const float*)phid, pln, (float*)px2);
    // 7) shared MLP: fused gu+SwiGLU -> act, then down-proj
    tc_gemm<256,2><<<dim3(FF/128, S/128, 1), 256, TC_SMEM_BYTES(256)>>>(
        (const float*)px2, sguw, nullptr, (float*)pact, S, FF, H, 0, 0, 0, nullptr);
    tc_gemm<128,0><<<dim3(H/128, S/128, 1), 256, TC_SMEM_BYTES(128)>>>(
        (const float*)pact, sdw, nullptr, (float*)pshared, S, H, FF, 0, 0, 0, nullptr);
    // 8) router + dispatch
    gate_kernel<<<S, 256>>>(gatew);
    slot_kernel<<<1, 512>>>();
    gather_kernel<<<dim3(CAP, NE), 192>>>();
    // 9) expert MLPs: fused gu+SwiGLU -> eact, then down-proj
    tc_gemm<256,2><<<dim3(FF/128, CAP/128, NE), 256, TC_SMEM_BYTES(256)>>>(
        (const float*)pxd, eguw, nullptr, (float*)peact, CAP, FF, H,
        (long long)CAP * H, (long long)2*FF * H, (long long)CAP * FF, (const int*)pcnt);
    tc_gemm<128,0><<<dim3(H/128, CAP/128, NE), 256, TC_SMEM_BYTES(128)>>>(
        (const float*)peact, edw, nullptr, (float*)peout, CAP, H, FF,
        (long long)CAP * FF, (long long)H * FF, (long long)CAP * H, (const int*)pcnt);
    // 10) combine
    combine_kernel<<<S, 256>>>(out);

    (void)in_sizes; (void)n_in; (void)out_size;
}